// round 1
// baseline (speedup 1.0000x reference)
#include <cuda_runtime.h>
#include <cuda_bf16.h>
#include <math.h>

// Problem constants
#define BB 4
#define TT 512
#define DD 1024
#define HH 8
#define DH 64
#define HD 512
#define PP 2048
#define NTOK (BB*TT)          // 2048 tokens

// ---------------- scratch (device globals; no allocation allowed) ----------
__device__ float g_xn  [NTOK*DD];   // layernormed input
__device__ float g_xt  [NTOK*PP];   // up-left proj
__device__ float g_r   [NTOK*HD];   // up-right proj (raw)
__device__ float g_xc  [NTOK*PP];   // conv + silu
__device__ float g_skip[NTOK*HD];
__device__ float g_q   [NTOK*HD];
__device__ float g_k   [NTOK*HD];   // raw (scaled in scan)
__device__ float g_v   [NTOK*HD];
__device__ float g_o   [NTOK*HD];   // raw (sigmoid in scan)
__device__ float g_ig  [NTOK*HH];
__device__ float g_fg  [NTOK*HH];
__device__ float g_comb[NTOK*HD];   // (hn+skip)*silu(r)

// ---------------- layernorm over D=1024 ------------------------------------
__global__ __launch_bounds__(256) void ln_kernel(
    const float* __restrict__ x, const float* __restrict__ w,
    const float* __restrict__ b, float* __restrict__ out)
{
    int t = blockIdx.x;
    const float* row = x + t * DD;
    float s = 0.f, s2 = 0.f;
    for (int i = threadIdx.x; i < DD; i += 256) {
        float v = row[i]; s += v; s2 += v * v;
    }
    __shared__ float sh[16];
    int warp = threadIdx.x >> 5, lane = threadIdx.x & 31;
    #pragma unroll
    for (int o = 16; o; o >>= 1) {
        s  += __shfl_xor_sync(0xffffffffu, s,  o);
        s2 += __shfl_xor_sync(0xffffffffu, s2, o);
    }
    if (lane == 0) { sh[warp] = s; sh[8 + warp] = s2; }
    __syncthreads();
    if (threadIdx.x == 0) {
        float ts = 0.f, ts2 = 0.f;
        #pragma unroll
        for (int i = 0; i < 8; i++) { ts += sh[i]; ts2 += sh[8 + i]; }
        float mu  = ts  * (1.f / DD);
        float var = ts2 * (1.f / DD) - mu * mu;
        sh[0] = mu; sh[1] = rsqrtf(var + 1e-6f);
    }
    __syncthreads();
    float mu = sh[0], rstd = sh[1];
    for (int i = threadIdx.x; i < DD; i += 256)
        out[t * DD + i] = (row[i] - mu) * rstd * w[i] + b[i];
}

// ---------------- 128x128x8 register-blocked SGEMM --------------------------
// C[M,N] = A[M,K] @ B[K,N] + bias ( + residual ). M,N multiples of 128, K of 8.
template<bool RES>
__global__ __launch_bounds__(256) void sgemm_kernel(
    const float* __restrict__ A, const float* __restrict__ B,
    const float* __restrict__ bias, const float* __restrict__ res,
    float* __restrict__ Cout, int M, int N, int K)
{
    __shared__ float As[8][128];
    __shared__ float Bs[8][128];
    const int tid = threadIdx.x;
    const int bm = blockIdx.y * 128;
    const int bn = blockIdx.x * 128;
    const int tx = tid & 15, ty = tid >> 4;
    const int arow = tid >> 1, acol = (tid & 1) << 2;
    const int brow = tid >> 5, bcol = (tid & 31) << 2;
    const float* Aptr = A + (bm + arow) * K + acol;
    const float* Bptr = B + brow * N + bn + bcol;

    float acc[8][8];
    #pragma unroll
    for (int i = 0; i < 8; i++)
        #pragma unroll
        for (int j = 0; j < 8; j++) acc[i][j] = 0.f;

    for (int k0 = 0; k0 < K; k0 += 8) {
        float4 a    = *(const float4*)(Aptr + k0);
        float4 bv   = *(const float4*)(Bptr + (size_t)k0 * N);
        As[acol + 0][arow] = a.x;
        As[acol + 1][arow] = a.y;
        As[acol + 2][arow] = a.z;
        As[acol + 3][arow] = a.w;
        *(float4*)&Bs[brow][bcol] = bv;
        __syncthreads();
        #pragma unroll
        for (int kk = 0; kk < 8; kk++) {
            float4 a0 = *(const float4*)&As[kk][ty * 8];
            float4 a1 = *(const float4*)&As[kk][ty * 8 + 4];
            float4 b0 = *(const float4*)&Bs[kk][tx * 8];
            float4 b1 = *(const float4*)&Bs[kk][tx * 8 + 4];
            float ar[8] = {a0.x, a0.y, a0.z, a0.w, a1.x, a1.y, a1.z, a1.w};
            float br[8] = {b0.x, b0.y, b0.z, b0.w, b1.x, b1.y, b1.z, b1.w};
            #pragma unroll
            for (int i = 0; i < 8; i++)
                #pragma unroll
                for (int j = 0; j < 8; j++)
                    acc[i][j] += ar[i] * br[j];
        }
        __syncthreads();
    }

    #pragma unroll
    for (int i = 0; i < 8; i++) {
        int row = bm + ty * 8 + i;
        #pragma unroll
        for (int j = 0; j < 8; j++) {
            int col = bn + tx * 8 + j;
            float vv = acc[i][j] + bias[col];
            if (RES) vv += res[(size_t)row * N + col];
            Cout[(size_t)row * N + col] = vv;
        }
    }
}

// ---- batched variant: 5 GEMMs of identical shape (M=2048,N=512,K=2048),
// blockIdx.z selects the job. One launch fills the chip.
struct Gemm5Jobs {
    const float* A[5];
    const float* B[5];
    const float* bias[5];
    float*       out[5];
};

__global__ __launch_bounds__(256) void sgemm5_kernel(Gemm5Jobs jobs)
{
    const int job = blockIdx.z;
    const float* __restrict__ A    = jobs.A[job];
    const float* __restrict__ B    = jobs.B[job];
    const float* __restrict__ bias = jobs.bias[job];
    float*       __restrict__ Cout = jobs.out[job];
    const int M = NTOK, N = HD, K = PP;

    __shared__ float As[8][128];
    __shared__ float Bs[8][128];
    const int tid = threadIdx.x;
    const int bm = blockIdx.y * 128;
    const int bn = blockIdx.x * 128;
    const int tx = tid & 15, ty = tid >> 4;
    const int arow = tid >> 1, acol = (tid & 1) << 2;
    const int brow = tid >> 5, bcol = (tid & 31) << 2;
    const float* Aptr = A + (bm + arow) * K + acol;
    const float* Bptr = B + brow * N + bn + bcol;

    float acc[8][8];
    #pragma unroll
    for (int i = 0; i < 8; i++)
        #pragma unroll
        for (int j = 0; j < 8; j++) acc[i][j] = 0.f;

    for (int k0 = 0; k0 < K; k0 += 8) {
        float4 a  = *(const float4*)(Aptr + k0);
        float4 bv = *(const float4*)(Bptr + (size_t)k0 * N);
        As[acol + 0][arow] = a.x;
        As[acol + 1][arow] = a.y;
        As[acol + 2][arow] = a.z;
        As[acol + 3][arow] = a.w;
        *(float4*)&Bs[brow][bcol] = bv;
        __syncthreads();
        #pragma unroll
        for (int kk = 0; kk < 8; kk++) {
            float4 a0 = *(const float4*)&As[kk][ty * 8];
            float4 a1 = *(const float4*)&As[kk][ty * 8 + 4];
            float4 b0 = *(const float4*)&Bs[kk][tx * 8];
            float4 b1 = *(const float4*)&Bs[kk][tx * 8 + 4];
            float ar[8] = {a0.x, a0.y, a0.z, a0.w, a1.x, a1.y, a1.z, a1.w};
            float br[8] = {b0.x, b0.y, b0.z, b0.w, b1.x, b1.y, b1.z, b1.w};
            #pragma unroll
            for (int i = 0; i < 8; i++)
                #pragma unroll
                for (int j = 0; j < 8; j++)
                    acc[i][j] += ar[i] * br[j];
        }
        __syncthreads();
    }

    #pragma unroll
    for (int i = 0; i < 8; i++) {
        int row = bm + ty * 8 + i;
        #pragma unroll
        for (int j = 0; j < 8; j++) {
            int col = bn + tx * 8 + j;
            Cout[(size_t)row * N + col] = acc[i][j] + bias[col];
        }
    }
}

// ---------------- causal conv over feature axis + silu ----------------------
__global__ __launch_bounds__(256) void conv_silu_kernel(
    const float* __restrict__ xt, const float* __restrict__ cw,
    const float* __restrict__ cb, float* __restrict__ xc)
{
    int t = blockIdx.x;
    int p = blockIdx.y * 256 + threadIdx.x;
    const float* row = xt + (size_t)t * PP;
    float w0 = cw[0], w1 = cw[1], w2 = cw[2], w3 = cw[3];
    float acc = row[p] * w3;
    if (p >= 1) acc += row[p - 1] * w2;
    if (p >= 2) acc += row[p - 2] * w1;
    if (p >= 3) acc += row[p - 3] * w0;
    acc += cb[0];
    xc[(size_t)t * PP + p] = acc / (1.f + expf(-acc));   // silu
}

// ---------------- i/f gates: 16 dots of length 2048 per token + softcap -----
__global__ __launch_bounds__(256) void gates_kernel(
    const float* __restrict__ xc,
    const float* __restrict__ Wi, const float* __restrict__ bi,
    const float* __restrict__ Wf, const float* __restrict__ bf,
    float* __restrict__ gi, float* __restrict__ gf)
{
    int t = blockIdx.x;
    int warp = threadIdx.x >> 5, lane = threadIdx.x & 31;
    const float* row = xc + (size_t)t * PP;
    float si = 0.f, sf = 0.f;
    for (int p = lane; p < PP; p += 32) {
        float xv = row[p];
        si += xv * Wi[p * HH + warp];
        sf += xv * Wf[p * HH + warp];
    }
    #pragma unroll
    for (int o = 16; o; o >>= 1) {
        si += __shfl_xor_sync(0xffffffffu, si, o);
        sf += __shfl_xor_sync(0xffffffffu, sf, o);
    }
    if (lane == 0) {
        float a  = si + bi[warp];
        float b2 = sf + bf[warp];
        gi[t * HH + warp] = 15.f * tanhf(a  * (1.f / 15.f));
        gf[t * HH + warp] = 15.f * tanhf(b2 * (1.f / 15.f));
    }
}

// ---------------- sequential mLSTM scan, one CTA per (b,h) ------------------
// Fuses: o-gate sigmoid, head layernorm, +skip, *silu(r)  ->  g_comb
__global__ __launch_bounds__(64) void scan_kernel(
    const float* __restrict__ q, const float* __restrict__ kraw,
    const float* __restrict__ v, const float* __restrict__ ig,
    const float* __restrict__ fg, const float* __restrict__ oraw,
    const float* __restrict__ skip, const float* __restrict__ rraw,
    const float* __restrict__ hlnw, const float* __restrict__ hlnb,
    float* __restrict__ outc)
{
    const int b = blockIdx.x >> 3, h = blockIdx.x & 7;
    const int d = threadIdx.x;
    const int w = d >> 5, lane = d & 31;

    float C[DH];
    #pragma unroll
    for (int e = 0; e < DH; e++) C[e] = 0.f;
    float n = 1.f;     // init ones
    float m = 0.f;     // init zeros

    __shared__ float qs[DH], ks[DH], vs[DH];
    __shared__ float bufA[2], bufB[2], bufC[2];

    const float lw = hlnw[h * DH + d];
    const float lb = hlnb[h * DH + d];

    for (int t = 0; t < TT; t++) {
        const int tb   = b * TT + t;
        const int base = (tb * HH + h) * DH + d;
        qs[d] = q[base];
        ks[d] = kraw[base] * 0.125f;     // 1/sqrt(64)
        vs[d] = v[base];
        const float it = ig[tb * HH + h];
        const float ft = fg[tb * HH + h];
        __syncthreads();

        // scalar gate math, computed redundantly by all 64 threads (no reduce)
        const float mt = fmaxf(ft + m, it);
        const float fe = expf(ft - mt + m);
        const float ie = expf(it - mt);
        m = mt;

        const float kd = ks[d], vd = vs[d], qd = qs[d];
        const float ievd = ie * vd;
        float n0 = 0.f, n1 = 0.f, n2 = 0.f, n3 = 0.f;
        #pragma unroll
        for (int e = 0; e < DH; e += 4) {
            C[e]   = fe * C[e]   + ievd * ks[e];   n0 += C[e]   * qs[e];
            C[e+1] = fe * C[e+1] + ievd * ks[e+1]; n1 += C[e+1] * qs[e+1];
            C[e+2] = fe * C[e+2] + ievd * ks[e+2]; n2 += C[e+2] * qs[e+2];
            C[e+3] = fe * C[e+3] + ievd * ks[e+3]; n3 += C[e+3] * qs[e+3];
        }
        const float num = (n0 + n1) + (n2 + n3);
        n = fe * n + ie * kd;

        // den = sum over e of n[e]*q[e]  (reduce over 64 threads)
        float den = n * qd;
        #pragma unroll
        for (int o = 16; o; o >>= 1) den += __shfl_xor_sync(0xffffffffu, den, o);
        if (lane == 0) bufA[w] = den;
        __syncthreads();
        den = bufA[0] + bufA[1];

        const float hval = num / fmaxf(den, 1.0f);
        const float ov = oraw[base];
        const float og = 1.f / (1.f + expf(-ov));
        const float hh = og * hval;

        // head layernorm stats over the 64 lanes
        float s1 = hh, s2 = hh * hh;
        #pragma unroll
        for (int o = 16; o; o >>= 1) {
            s1 += __shfl_xor_sync(0xffffffffu, s1, o);
            s2 += __shfl_xor_sync(0xffffffffu, s2, o);
        }
        if (lane == 0) { bufB[w] = s1; bufC[w] = s2; }
        __syncthreads();
        s1 = bufB[0] + bufB[1];
        s2 = bufC[0] + bufC[1];
        const float mu  = s1 * (1.f / DH);
        const float var = s2 * (1.f / DH) - mu * mu;
        const float hn  = (hh - mu) * rsqrtf(var + 1e-6f) * lw + lb;

        const int oidx = tb * HD + h * DH + d;
        const float rv  = rraw[oidx];
        const float sil = rv / (1.f + expf(-rv));
        outc[oidx] = (hn + skip[oidx]) * sil;
        __syncthreads();   // protect qs/ks/vs/buf* before next iteration
    }
}

// ---------------------------------------------------------------------------
extern "C" void kernel_launch(void* const* d_in, const int* in_sizes, int n_in,
                              void* d_out, int out_size)
{
    const float* x      = (const float*)d_in[0];
    const float* ln_w   = (const float*)d_in[1];
    const float* ln_b   = (const float*)d_in[2];
    const float* hln_w  = (const float*)d_in[3];
    const float* hln_b  = (const float*)d_in[4];
    const float* Wl     = (const float*)d_in[5];
    const float* bl     = (const float*)d_in[6];
    const float* Wr     = (const float*)d_in[7];
    const float* br     = (const float*)d_in[8];
    const float* conv_w = (const float*)d_in[9];
    const float* conv_b = (const float*)d_in[10];
    const float* Wskip  = (const float*)d_in[11];
    const float* bskip  = (const float*)d_in[12];
    const float* Wi     = (const float*)d_in[13];
    const float* bi     = (const float*)d_in[14];
    const float* Wf     = (const float*)d_in[15];
    const float* bf     = (const float*)d_in[16];
    const float* Wo     = (const float*)d_in[17];
    const float* bo     = (const float*)d_in[18];
    const float* Wq     = (const float*)d_in[19];
    const float* bq     = (const float*)d_in[20];
    const float* Wk     = (const float*)d_in[21];
    const float* bk     = (const float*)d_in[22];
    const float* Wv     = (const float*)d_in[23];
    const float* bv     = (const float*)d_in[24];
    const float* Wd     = (const float*)d_in[25];
    const float* bd     = (const float*)d_in[26];
    float* out = (float*)d_out;

    float *xn, *xt, *r, *xc, *skip, *q, *k, *v, *o, *gi, *gf, *comb;
    cudaGetSymbolAddress((void**)&xn,   g_xn);
    cudaGetSymbolAddress((void**)&xt,   g_xt);
    cudaGetSymbolAddress((void**)&r,    g_r);
    cudaGetSymbolAddress((void**)&xc,   g_xc);
    cudaGetSymbolAddress((void**)&skip, g_skip);
    cudaGetSymbolAddress((void**)&q,    g_q);
    cudaGetSymbolAddress((void**)&k,    g_k);
    cudaGetSymbolAddress((void**)&v,    g_v);
    cudaGetSymbolAddress((void**)&o,    g_o);
    cudaGetSymbolAddress((void**)&gi,   g_ig);
    cudaGetSymbolAddress((void**)&gf,   g_fg);
    cudaGetSymbolAddress((void**)&comb, g_comb);

    // 1. layernorm
    ln_kernel<<<NTOK, 256>>>(x, ln_w, ln_b, xn);

    // 2. xt = xn @ Wl + bl   (2048 x 2048 x 1024)
    sgemm_kernel<false><<<dim3(PP / 128, NTOK / 128), 256>>>(
        xn, Wl, bl, nullptr, xt, NTOK, PP, DD);

    // 3. r = xn @ Wr + br    (2048 x 512 x 1024)
    sgemm_kernel<false><<<dim3(HD / 128, NTOK / 128), 256>>>(
        xn, Wr, br, nullptr, r, NTOK, HD, DD);

    // 4. causal feature-conv + silu
    conv_silu_kernel<<<dim3(NTOK, PP / 256), 256>>>(xt, conv_w, conv_b, xc);

    // 5. five P->HD projections in one batched launch:
    //    skip,q,k from xc ; v,o from xt
    Gemm5Jobs jobs;
    jobs.A[0] = xc; jobs.B[0] = Wskip; jobs.bias[0] = bskip; jobs.out[0] = skip;
    jobs.A[1] = xc; jobs.B[1] = Wq;    jobs.bias[1] = bq;    jobs.out[1] = q;
    jobs.A[2] = xc; jobs.B[2] = Wk;    jobs.bias[2] = bk;    jobs.out[2] = k;
    jobs.A[3] = xt; jobs.B[3] = Wv;    jobs.bias[3] = bv;    jobs.out[3] = v;
    jobs.A[4] = xt; jobs.B[4] = Wo;    jobs.bias[4] = bo;    jobs.out[4] = o;
    sgemm5_kernel<<<dim3(HD / 128, NTOK / 128, 5), 256>>>(jobs);

    // 6. i/f gates (+softcap)
    gates_kernel<<<NTOK, 256>>>(xc, Wi, bi, Wf, bf, gi, gf);

    // 7. recurrent scan, fused epilogue -> comb
    scan_kernel<<<BB * HH, 64>>>(q, k, v, gi, gf, o, skip, r,
                                 hln_w, hln_b, comb);

    // 8. out = comb @ Wd + bd + x   (2048 x 1024 x 512, residual fused)
    sgemm_kernel<true><<<dim3(DD / 128, NTOK / 128), 256>>>(
        comb, Wd, bd, x, out, NTOK, DD, HD);
}

// round 5
// speedup vs baseline: 1.9213x; 1.9213x over previous
#include <cuda_runtime.h>
#include <cuda_bf16.h>
#include <cstdint>
#include <math.h>

typedef __nv_bfloat16 bf16;

// Problem constants
#define BB 4
#define TT 512
#define DD 1024
#define HH 8
#define DH 64
#define HD 512
#define PP 2048
#define NTOK (BB*TT)          // 2048 tokens

// ================= scratch (device globals) =================================
__device__ bf16  g_xn_h[NTOK*DD], g_xn_l[NTOK*DD];
__device__ float g_xt  [NTOK*PP];
__device__ bf16  g_xt_h[NTOK*PP], g_xt_l[NTOK*PP];
__device__ float g_xc  [NTOK*PP];
__device__ bf16  g_xc_h[NTOK*PP], g_xc_l[NTOK*PP];
__device__ float g_r   [NTOK*HD], g_skip[NTOK*HD];
__device__ float g_q   [NTOK*HD], g_k   [NTOK*HD];
__device__ float g_v   [NTOK*HD], g_o   [NTOK*HD];
__device__ float g_ig  [NTOK*HH], g_fg  [NTOK*HH];
__device__ bf16  g_cm_h[NTOK*HD], g_cm_l[NTOK*HD];
// transposed + split weights: WT[N,K]
__device__ bf16 g_WlT_h[PP*DD], g_WlT_l[PP*DD];
__device__ bf16 g_WrT_h[HD*DD], g_WrT_l[HD*DD];
__device__ bf16 g_WsT_h[HD*PP], g_WsT_l[HD*PP];
__device__ bf16 g_WqT_h[HD*PP], g_WqT_l[HD*PP];
__device__ bf16 g_WkT_h[HD*PP], g_WkT_l[HD*PP];
__device__ bf16 g_WvT_h[HD*PP], g_WvT_l[HD*PP];
__device__ bf16 g_WoT_h[HD*PP], g_WoT_l[HD*PP];
__device__ bf16 g_WdT_h[DD*HD], g_WdT_l[DD*HD];

__device__ __forceinline__ void split_store(float v, bf16* ph, bf16* pl, size_t i) {
    bf16 h = __float2bfloat16(v);
    ph[i] = h;
    pl[i] = __float2bfloat16(v - __bfloat162float(h));
}

__device__ __forceinline__ uint32_t smem_u32(const void* p) {
    uint32_t a;
    asm("{ .reg .u64 t; cvta.to.shared.u64 t, %1; cvt.u32.u64 %0, t; }"
        : "=r"(a) : "l"(p));
    return a;
}
__device__ __forceinline__ void cp16(uint32_t s, const void* g) {
    asm volatile("cp.async.cg.shared.global [%0], [%1], 16;" :: "r"(s), "l"(g));
}
__device__ __forceinline__ void ldm4(uint32_t addr, uint32_t* r) {
    asm volatile("ldmatrix.sync.aligned.m8n8.x4.shared.b16 {%0,%1,%2,%3}, [%4];"
                 : "=r"(r[0]), "=r"(r[1]), "=r"(r[2]), "=r"(r[3]) : "r"(addr));
}
__device__ __forceinline__ void mma16816(float* c, const uint32_t* a,
                                         uint32_t b0, uint32_t b1) {
    asm volatile("mma.sync.aligned.m16n8k16.row.col.f32.bf16.bf16.f32 "
        "{%0,%1,%2,%3}, {%4,%5,%6,%7}, {%8,%9}, {%0,%1,%2,%3};"
        : "+f"(c[0]), "+f"(c[1]), "+f"(c[2]), "+f"(c[3])
        : "r"(a[0]), "r"(a[1]), "r"(a[2]), "r"(a[3]), "r"(b0), "r"(b1));
}

// ================= layernorm + bf16 split ==================================
__global__ __launch_bounds__(256) void ln_split_kernel(
    const float* __restrict__ x, const float* __restrict__ w,
    const float* __restrict__ b, bf16* __restrict__ oh, bf16* __restrict__ ol)
{
    int t = blockIdx.x;
    const float* row = x + (size_t)t * DD;
    float s = 0.f, s2 = 0.f;
    for (int i = threadIdx.x; i < DD; i += 256) {
        float v = row[i]; s += v; s2 += v * v;
    }
    __shared__ float sh[16];
    int warp = threadIdx.x >> 5, lane = threadIdx.x & 31;
    #pragma unroll
    for (int o = 16; o; o >>= 1) {
        s  += __shfl_xor_sync(0xffffffffu, s,  o);
        s2 += __shfl_xor_sync(0xffffffffu, s2, o);
    }
    if (lane == 0) { sh[warp] = s; sh[8 + warp] = s2; }
    __syncthreads();
    if (threadIdx.x == 0) {
        float ts = 0.f, ts2 = 0.f;
        #pragma unroll
        for (int i = 0; i < 8; i++) { ts += sh[i]; ts2 += sh[8 + i]; }
        float mu  = ts  * (1.f / DD);
        float var = ts2 * (1.f / DD) - mu * mu;
        sh[0] = mu; sh[1] = rsqrtf(var + 1e-6f);
    }
    __syncthreads();
    float mu = sh[0], rstd = sh[1];
    for (int i = threadIdx.x; i < DD; i += 256) {
        float y = (row[i] - mu) * rstd * w[i] + b[i];
        split_store(y, oh, ol, (size_t)t * DD + i);
    }
}

// ================= weight transpose + split ================================
// W[K,N] row-major -> WT_h/WT_l [N,K]
__global__ __launch_bounds__(256) void prep_w_kernel(
    const float* __restrict__ W, bf16* __restrict__ Th, bf16* __restrict__ Tl,
    int K, int N)
{
    __shared__ float tile[32][33];
    int n0 = blockIdx.x * 32, k0 = blockIdx.y * 32;
    int tx = threadIdx.x & 31, ty = threadIdx.x >> 5;
    for (int r = ty; r < 32; r += 8)
        tile[r][tx] = W[(size_t)(k0 + r) * N + n0 + tx];
    __syncthreads();
    for (int r = ty; r < 32; r += 8) {
        float v = tile[tx][r];   // W[k0+tx][n0+r]
        split_store(v, Th, Tl, (size_t)(n0 + r) * K + k0 + tx);
    }
}

// ================= mma.sync split-bf16 GEMM ================================
// D[M,N] = A[M,K] @ W[K,N] + bias (+res). A as hi/lo bf16 [M,K], W as
// transposed hi/lo bf16 [N,K]. BM=BN=128, BK=32, cp.async double-buffered.
// 3 passes: Ah*Bh + Ah*Bl + Al*Bh.
struct GemmJob {
    const bf16 *Ah, *Al, *Bh, *Bl;
    const float *bias, *res;
    float *out;
    bf16 *oh, *ol;
};
struct GemmParams { GemmJob jobs[5]; int K; };

#define PADK 40                        // halves per smem row (32 + 8 pad)
#define OPT  (128*PADK)                // halves per operand tile
#define STG  (4*OPT)                   // halves per stage (Ah,Al,Bh,Bl)
#define GSMEM_BYTES (2*STG*2)          // 81920 B

__global__ __launch_bounds__(256, 1) void gemm_mma_kernel(GemmParams p)
{
    extern __shared__ bf16 smg[];
    const uint32_t sbase = smem_u32(smg);
    const GemmJob J = p.jobs[blockIdx.z];
    const int K = p.K;
    const int N = gridDim.x * 128;
    const int bm = blockIdx.y * 128, bn = blockIdx.x * 128;
    const int tid = threadIdx.x, lane = tid & 31, wid = tid >> 5;
    const int warpM = wid & 3, warpN = wid >> 2;    // 4 x 2 warps, tile 32x64

    const bf16* gsrc[4];
    gsrc[0] = J.Ah + (size_t)bm * K;
    gsrc[1] = J.Al + (size_t)bm * K;
    gsrc[2] = J.Bh + (size_t)bn * K;
    gsrc[3] = J.Bl + (size_t)bn * K;

    // loader: 2 threads per row; each thread 2x16B chunks
    const int lrow = tid >> 1;
    const int lcol = (tid & 1) * 16;   // element offset (0 or 16)
    const uint32_t swr = sbase + (uint32_t)(lrow * PADK + lcol) * 2;

    float acc[2][8][4];
    #pragma unroll
    for (int i = 0; i < 2; i++)
        #pragma unroll
        for (int j = 0; j < 8; j++)
            #pragma unroll
            for (int e = 0; e < 4; e++) acc[i][j][e] = 0.f;

    const int NT = K / 32;

    // ---- preload stage 0
    {
        #pragma unroll
        for (int w = 0; w < 4; w++) {
            const bf16* g = gsrc[w] + (size_t)lrow * K + lcol;
            uint32_t s = swr + (uint32_t)(w * OPT) * 2;
            cp16(s, g); cp16(s + 16, g + 8);
        }
        asm volatile("cp.async.commit_group;");
    }

    int buf = 0;
    for (int kt = 0; kt < NT; kt++) {
        if (kt + 1 < NT) {
            const int k0 = (kt + 1) * 32;
            #pragma unroll
            for (int w = 0; w < 4; w++) {
                const bf16* g = gsrc[w] + (size_t)lrow * K + k0 + lcol;
                uint32_t s = swr + (uint32_t)((buf ^ 1) * STG + w * OPT) * 2;
                cp16(s, g); cp16(s + 16, g + 8);
            }
            asm volatile("cp.async.commit_group;");
            asm volatile("cp.async.wait_group 1;");
        } else {
            asm volatile("cp.async.wait_group 0;");
        }
        __syncthreads();

        const uint32_t stg = sbase + (uint32_t)(buf * STG) * 2;
        #pragma unroll
        for (int ks = 0; ks < 2; ks++) {
            const int koff = ks * 16 + ((lane >> 4) << 3);
            const int rsel = lane & 15;
            uint32_t a[2][2][4], b[2][4][4];
            #pragma unroll
            for (int op = 0; op < 2; op++)
                #pragma unroll
                for (int i = 0; i < 2; i++) {
                    const int row = warpM * 32 + i * 16 + rsel;
                    ldm4(stg + (uint32_t)(op * OPT + row * PADK + koff) * 2,
                         a[op][i]);
                }
            #pragma unroll
            for (int op = 0; op < 2; op++)
                #pragma unroll
                for (int j = 0; j < 4; j++) {
                    const int row = warpN * 64 + j * 16 + rsel;
                    ldm4(stg + (uint32_t)((2 + op) * OPT + row * PADK + koff) * 2,
                         b[op][j]);
                }
            // passes: (Ah,Bh), (Ah,Bl), (Al,Bh)
            #pragma unroll
            for (int ps = 0; ps < 3; ps++) {
                const int aop = (ps == 2) ? 1 : 0;
                const int bop = (ps == 1) ? 1 : 0;
                #pragma unroll
                for (int i = 0; i < 2; i++)
                    #pragma unroll
                    for (int j = 0; j < 8; j++)
                        mma16816(acc[i][j], a[aop][i],
                                 b[bop][j >> 1][j & 1],
                                 b[bop][j >> 1][(j & 1) + 2]);
            }
        }
        __syncthreads();
        buf ^= 1;
    }

    // ---- epilogue
    const int er = (lane >> 2);
    const int ec = (lane & 3) * 2;
    #pragma unroll
    for (int i = 0; i < 2; i++) {
        #pragma unroll
        for (int j = 0; j < 8; j++) {
            const int row0 = bm + warpM * 32 + i * 16 + er;
            const int col0 = bn + warpN * 64 + j * 8 + ec;
            #pragma unroll
            for (int e = 0; e < 4; e++) {
                const int row = row0 + (e >> 1) * 8;
                const int col = col0 + (e & 1);
                float v = acc[i][j][e] + J.bias[col];
                if (J.res) v += J.res[(size_t)row * N + col];
                const size_t idx = (size_t)row * N + col;
                J.out[idx] = v;
                if (J.oh) split_store(v, J.oh, J.ol, idx);
            }
        }
    }
}

// ================= causal feature-conv + silu + split ======================
__global__ __launch_bounds__(256) void conv_silu_kernel(
    const float* __restrict__ xt, const float* __restrict__ cw,
    const float* __restrict__ cbp, float* __restrict__ xc,
    bf16* __restrict__ xch, bf16* __restrict__ xcl)
{
    int t = blockIdx.x;
    int pcol = blockIdx.y * 256 + threadIdx.x;
    const float* row = xt + (size_t)t * PP;
    float w0 = cw[0], w1 = cw[1], w2 = cw[2], w3 = cw[3];
    float acc = row[pcol] * w3;
    if (pcol >= 1) acc += row[pcol - 1] * w2;
    if (pcol >= 2) acc += row[pcol - 2] * w1;
    if (pcol >= 3) acc += row[pcol - 3] * w0;
    acc += cbp[0];
    float y = acc / (1.f + expf(-acc));
    size_t idx = (size_t)t * PP + pcol;
    xc[idx] = y;
    split_store(y, xch, xcl, idx);
}

// ================= i/f gates ===============================================
__global__ __launch_bounds__(256) void gates_kernel(
    const float* __restrict__ xc,
    const float* __restrict__ Wi, const float* __restrict__ bi,
    const float* __restrict__ Wf, const float* __restrict__ bf_,
    float* __restrict__ gi, float* __restrict__ gf)
{
    int t = blockIdx.x;
    int warp = threadIdx.x >> 5, lane = threadIdx.x & 31;
    const float* row = xc + (size_t)t * PP;
    float si = 0.f, sf = 0.f;
    for (int p = lane; p < PP; p += 32) {
        float xv = row[p];
        si += xv * Wi[p * HH + warp];
        sf += xv * Wf[p * HH + warp];
    }
    #pragma unroll
    for (int o = 16; o; o >>= 1) {
        si += __shfl_xor_sync(0xffffffffu, si, o);
        sf += __shfl_xor_sync(0xffffffffu, sf, o);
    }
    if (lane == 0) {
        float a  = si + bi[warp];
        float b2 = sf + bf_[warp];
        gi[t * HH + warp] = 15.f * tanhf(a  * (1.f / 15.f));
        gf[t * HH + warp] = 15.f * tanhf(b2 * (1.f / 15.f));
    }
}

// ================= recurrent scan (fused epilogue, split output) ===========
__global__ __launch_bounds__(64) void scan_kernel(
    const float* __restrict__ q, const float* __restrict__ kraw,
    const float* __restrict__ v, const float* __restrict__ ig,
    const float* __restrict__ fg, const float* __restrict__ oraw,
    const float* __restrict__ skip, const float* __restrict__ rraw,
    const float* __restrict__ hlnw, const float* __restrict__ hlnb,
    bf16* __restrict__ outh, bf16* __restrict__ outl)
{
    const int b = blockIdx.x >> 3, h = blockIdx.x & 7;
    const int d = threadIdx.x;
    const int w = d >> 5, lane = d & 31;

    float C[DH];
    #pragma unroll
    for (int e = 0; e < DH; e++) C[e] = 0.f;
    float n = 1.f, m = 0.f;

    __shared__ float qs[DH], ks[DH], vs[DH];
    __shared__ float bufA[2], bufB[2], bufC[2];

    const float lw = hlnw[h * DH + d];
    const float lb = hlnb[h * DH + d];

    for (int t = 0; t < TT; t++) {
        const int tb   = b * TT + t;
        const int base = (tb * HH + h) * DH + d;
        qs[d] = q[base];
        ks[d] = kraw[base] * 0.125f;
        vs[d] = v[base];
        const float it = ig[tb * HH + h];
        const float ft = fg[tb * HH + h];
        __syncthreads();

        const float mt = fmaxf(ft + m, it);
        const float fe = expf(ft - mt + m);
        const float ie = expf(it - mt);
        m = mt;

        const float kd = ks[d], vd = vs[d], qd = qs[d];
        const float ievd = ie * vd;
        float n0 = 0.f, n1 = 0.f, n2 = 0.f, n3 = 0.f;
        #pragma unroll
        for (int e = 0; e < DH; e += 4) {
            C[e]   = fe * C[e]   + ievd * ks[e];   n0 += C[e]   * qs[e];
            C[e+1] = fe * C[e+1] + ievd * ks[e+1]; n1 += C[e+1] * qs[e+1];
            C[e+2] = fe * C[e+2] + ievd * ks[e+2]; n2 += C[e+2] * qs[e+2];
            C[e+3] = fe * C[e+3] + ievd * ks[e+3]; n3 += C[e+3] * qs[e+3];
        }
        const float num = (n0 + n1) + (n2 + n3);
        n = fe * n + ie * kd;

        float den = n * qd;
        #pragma unroll
        for (int o = 16; o; o >>= 1) den += __shfl_xor_sync(0xffffffffu, den, o);
        if (lane == 0) bufA[w] = den;
        __syncthreads();
        den = bufA[0] + bufA[1];

        const float hval = num / fmaxf(den, 1.0f);
        const float ov = oraw[base];
        const float og = 1.f / (1.f + expf(-ov));
        const float hh = og * hval;

        float s1 = hh, s2 = hh * hh;
        #pragma unroll
        for (int o = 16; o; o >>= 1) {
            s1 += __shfl_xor_sync(0xffffffffu, s1, o);
            s2 += __shfl_xor_sync(0xffffffffu, s2, o);
        }
        if (lane == 0) { bufB[w] = s1; bufC[w] = s2; }
        __syncthreads();
        s1 = bufB[0] + bufB[1];
        s2 = bufC[0] + bufC[1];
        const float mu  = s1 * (1.f / DH);
        const float var = s2 * (1.f / DH) - mu * mu;
        const float hn  = (hh - mu) * rsqrtf(var + 1e-6f) * lw + lb;

        const int oidx = tb * HD + h * DH + d;
        const float rv  = rraw[oidx];
        const float sil = rv / (1.f + expf(-rv));
        const float val = (hn + skip[oidx]) * sil;
        split_store(val, outh, outl, oidx);
        __syncthreads();
    }
}

// ===========================================================================
extern "C" void kernel_launch(void* const* d_in, const int* in_sizes, int n_in,
                              void* d_out, int out_size)
{
    const float* x      = (const float*)d_in[0];
    const float* ln_w   = (const float*)d_in[1];
    const float* ln_b   = (const float*)d_in[2];
    const float* hln_w  = (const float*)d_in[3];
    const float* hln_b  = (const float*)d_in[4];
    const float* Wl     = (const float*)d_in[5];
    const float* bl     = (const float*)d_in[6];
    const float* Wr     = (const float*)d_in[7];
    const float* br     = (const float*)d_in[8];
    const float* conv_w = (const float*)d_in[9];
    const float* conv_b = (const float*)d_in[10];
    const float* Wskip  = (const float*)d_in[11];
    const float* bskip  = (const float*)d_in[12];
    const float* Wi     = (const float*)d_in[13];
    const float* bi     = (const float*)d_in[14];
    const float* Wf     = (const float*)d_in[15];
    const float* bf_    = (const float*)d_in[16];
    const float* Wo     = (const float*)d_in[17];
    const float* bo     = (const float*)d_in[18];
    const float* Wq     = (const float*)d_in[19];
    const float* bq     = (const float*)d_in[20];
    const float* Wk     = (const float*)d_in[21];
    const float* bk     = (const float*)d_in[22];
    const float* Wv     = (const float*)d_in[23];
    const float* bv     = (const float*)d_in[24];
    const float* Wd     = (const float*)d_in[25];
    const float* bd     = (const float*)d_in[26];
    float* out = (float*)d_out;

    bf16 *xn_h, *xn_l, *xt_h, *xt_l, *xc_h, *xc_l, *cm_h, *cm_l;
    bf16 *WlT_h, *WlT_l, *WrT_h, *WrT_l, *WsT_h, *WsT_l, *WqT_h, *WqT_l;
    bf16 *WkT_h, *WkT_l, *WvT_h, *WvT_l, *WoT_h, *WoT_l, *WdT_h, *WdT_l;
    float *xt, *xc, *r, *skip, *q, *k, *v, *o, *gi, *gf;
    cudaGetSymbolAddress((void**)&xn_h, g_xn_h);  cudaGetSymbolAddress((void**)&xn_l, g_xn_l);
    cudaGetSymbolAddress((void**)&xt,   g_xt);
    cudaGetSymbolAddress((void**)&xt_h, g_xt_h);  cudaGetSymbolAddress((void**)&xt_l, g_xt_l);
    cudaGetSymbolAddress((void**)&xc,   g_xc);
    cudaGetSymbolAddress((void**)&xc_h, g_xc_h);  cudaGetSymbolAddress((void**)&xc_l, g_xc_l);
    cudaGetSymbolAddress((void**)&r,    g_r);     cudaGetSymbolAddress((void**)&skip, g_skip);
    cudaGetSymbolAddress((void**)&q,    g_q);     cudaGetSymbolAddress((void**)&k,    g_k);
    cudaGetSymbolAddress((void**)&v,    g_v);     cudaGetSymbolAddress((void**)&o,    g_o);
    cudaGetSymbolAddress((void**)&gi,   g_ig);    cudaGetSymbolAddress((void**)&gf,   g_fg);
    cudaGetSymbolAddress((void**)&cm_h, g_cm_h);  cudaGetSymbolAddress((void**)&cm_l, g_cm_l);
    cudaGetSymbolAddress((void**)&WlT_h, g_WlT_h); cudaGetSymbolAddress((void**)&WlT_l, g_WlT_l);
    cudaGetSymbolAddress((void**)&WrT_h, g_WrT_h); cudaGetSymbolAddress((void**)&WrT_l, g_WrT_l);
    cudaGetSymbolAddress((void**)&WsT_h, g_WsT_h); cudaGetSymbolAddress((void**)&WsT_l, g_WsT_l);
    cudaGetSymbolAddress((void**)&WqT_h, g_WqT_h); cudaGetSymbolAddress((void**)&WqT_l, g_WqT_l);
    cudaGetSymbolAddress((void**)&WkT_h, g_WkT_h); cudaGetSymbolAddress((void**)&WkT_l, g_WkT_l);
    cudaGetSymbolAddress((void**)&WvT_h, g_WvT_h); cudaGetSymbolAddress((void**)&WvT_l, g_WvT_l);
    cudaGetSymbolAddress((void**)&WoT_h, g_WoT_h); cudaGetSymbolAddress((void**)&WoT_l, g_WoT_l);
    cudaGetSymbolAddress((void**)&WdT_h, g_WdT_h); cudaGetSymbolAddress((void**)&WdT_l, g_WdT_l);

    cudaFuncSetAttribute(gemm_mma_kernel,
                         cudaFuncAttributeMaxDynamicSharedMemorySize, GSMEM_BYTES);

    // weight prep: transpose + bf16 split
    prep_w_kernel<<<dim3(PP/32, DD/32), 256>>>(Wl,    WlT_h, WlT_l, DD, PP);
    prep_w_kernel<<<dim3(HD/32, DD/32), 256>>>(Wr,    WrT_h, WrT_l, DD, HD);
    prep_w_kernel<<<dim3(HD/32, PP/32), 256>>>(Wskip, WsT_h, WsT_l, PP, HD);
    prep_w_kernel<<<dim3(HD/32, PP/32), 256>>>(Wq,    WqT_h, WqT_l, PP, HD);
    prep_w_kernel<<<dim3(HD/32, PP/32), 256>>>(Wk,    WkT_h, WkT_l, PP, HD);
    prep_w_kernel<<<dim3(HD/32, PP/32), 256>>>(Wv,    WvT_h, WvT_l, PP, HD);
    prep_w_kernel<<<dim3(HD/32, PP/32), 256>>>(Wo,    WoT_h, WoT_l, PP, HD);
    prep_w_kernel<<<dim3(DD/32, HD/32), 256>>>(Wd,    WdT_h, WdT_l, HD, DD);

    // 1. layernorm -> xn splits
    ln_split_kernel<<<NTOK, 256>>>(x, ln_w, ln_b, xn_h, xn_l);

    // 2. xt = xn @ Wl + bl (f32 + splits)
    {
        GemmParams p{}; p.K = DD;
        p.jobs[0] = { xn_h, xn_l, WlT_h, WlT_l, bl, nullptr, xt, xt_h, xt_l };
        gemm_mma_kernel<<<dim3(PP/128, NTOK/128, 1), 256, GSMEM_BYTES>>>(p);
    }
    // 3. r = xn @ Wr + br
    {
        GemmParams p{}; p.K = DD;
        p.jobs[0] = { xn_h, xn_l, WrT_h, WrT_l, br, nullptr, r, nullptr, nullptr };
        gemm_mma_kernel<<<dim3(HD/128, NTOK/128, 1), 256, GSMEM_BYTES>>>(p);
    }
    // 4. conv + silu -> xc (f32 + splits)
    conv_silu_kernel<<<dim3(NTOK, PP/256), 256>>>(xt, conv_w, conv_b, xc, xc_h, xc_l);

    // 5. five P->HD projections in one batched launch
    {
        GemmParams p{}; p.K = PP;
        p.jobs[0] = { xc_h, xc_l, WsT_h, WsT_l, bskip, nullptr, skip, nullptr, nullptr };
        p.jobs[1] = { xc_h, xc_l, WqT_h, WqT_l, bq,    nullptr, q,    nullptr, nullptr };
        p.jobs[2] = { xc_h, xc_l, WkT_h, WkT_l, bk,    nullptr, k,    nullptr, nullptr };
        p.jobs[3] = { xt_h, xt_l, WvT_h, WvT_l, bv,    nullptr, v,    nullptr, nullptr };
        p.jobs[4] = { xt_h, xt_l, WoT_h, WoT_l, bo,    nullptr, o,    nullptr, nullptr };
        gemm_mma_kernel<<<dim3(HD/128, NTOK/128, 5), 256, GSMEM_BYTES>>>(p);
    }
    // 6. i/f gates
    gates_kernel<<<NTOK, 256>>>(xc, Wi, bi, Wf, bf_, gi, gf);

    // 7. recurrent scan -> comb splits
    scan_kernel<<<BB * HH, 64>>>(q, k, v, gi, gf, o, skip, r,
                                 hln_w, hln_b, cm_h, cm_l);

    // 8. out = comb @ Wd + bd + x
    {
        GemmParams p{}; p.K = HD;
        p.jobs[0] = { cm_h, cm_l, WdT_h, WdT_l, bd, x, out, nullptr, nullptr };
        gemm_mma_kernel<<<dim3(DD/128, NTOK/128, 1), 256, GSMEM_BYTES>>>(p);
    }
}

// round 7
// speedup vs baseline: 3.6940x; 1.9227x over previous
#include <cuda_runtime.h>
#include <cuda_bf16.h>
#include <cstdint>
#include <math.h>

typedef __nv_bfloat16 bf16;

// Problem constants
#define BB 4
#define TT 512
#define DD 1024
#define HH 8
#define DH 64
#define HD 512
#define PP 2048
#define NTOK (BB*TT)          // 2048 tokens

// ================= scratch (device globals) =================================
__device__ bf16  g_xn_h[NTOK*DD], g_xn_l[NTOK*DD];
__device__ float g_xt  [NTOK*PP];
__device__ bf16  g_xt_h[NTOK*PP], g_xt_l[NTOK*PP];
__device__ float g_xc  [NTOK*PP];
__device__ bf16  g_xc_h[NTOK*PP], g_xc_l[NTOK*PP];
__device__ float g_r   [NTOK*HD], g_skip[NTOK*HD];
__device__ float g_q   [NTOK*HD], g_k   [NTOK*HD];
__device__ float g_v   [NTOK*HD], g_o   [NTOK*HD];
__device__ float g_ig  [NTOK*HH], g_fg  [NTOK*HH];
__device__ float g_a   [BB*HH*TT], g_M [BB*HH*TT];
__device__ bf16  g_cm_h[NTOK*HD], g_cm_l[NTOK*HD];
// transposed + split weights: WT[N,K]
__device__ bf16 g_WlT_h[PP*DD], g_WlT_l[PP*DD];
__device__ bf16 g_WrT_h[HD*DD], g_WrT_l[HD*DD];
__device__ bf16 g_WsT_h[HD*PP], g_WsT_l[HD*PP];
__device__ bf16 g_WqT_h[HD*PP], g_WqT_l[HD*PP];
__device__ bf16 g_WkT_h[HD*PP], g_WkT_l[HD*PP];
__device__ bf16 g_WvT_h[HD*PP], g_WvT_l[HD*PP];
__device__ bf16 g_WoT_h[HD*PP], g_WoT_l[HD*PP];
__device__ bf16 g_WdT_h[DD*HD], g_WdT_l[DD*HD];

__device__ __forceinline__ void split_store(float v, bf16* ph, bf16* pl, size_t i) {
    bf16 h = __float2bfloat16(v);
    ph[i] = h;
    pl[i] = __float2bfloat16(v - __bfloat162float(h));
}

__device__ __forceinline__ uint32_t smem_u32(const void* p) {
    uint32_t a;
    asm("{ .reg .u64 t; cvta.to.shared.u64 t, %1; cvt.u32.u64 %0, t; }"
        : "=r"(a) : "l"(p));
    return a;
}
__device__ __forceinline__ void cp16(uint32_t s, const void* g) {
    asm volatile("cp.async.cg.shared.global [%0], [%1], 16;" :: "r"(s), "l"(g));
}
__device__ __forceinline__ void ldm4(uint32_t addr, uint32_t* r) {
    asm volatile("ldmatrix.sync.aligned.m8n8.x4.shared.b16 {%0,%1,%2,%3}, [%4];"
                 : "=r"(r[0]), "=r"(r[1]), "=r"(r[2]), "=r"(r[3]) : "r"(addr));
}
__device__ __forceinline__ void mma16816(float* c, const uint32_t* a,
                                         uint32_t b0, uint32_t b1) {
    asm volatile("mma.sync.aligned.m16n8k16.row.col.f32.bf16.bf16.f32 "
        "{%0,%1,%2,%3}, {%4,%5,%6,%7}, {%8,%9}, {%0,%1,%2,%3};"
        : "+f"(c[0]), "+f"(c[1]), "+f"(c[2]), "+f"(c[3])
        : "r"(a[0]), "r"(a[1]), "r"(a[2]), "r"(a[3]), "r"(b0), "r"(b1));
}

// ================= layernorm + bf16 split ==================================
__global__ __launch_bounds__(256) void ln_split_kernel(
    const float* __restrict__ x, const float* __restrict__ w,
    const float* __restrict__ b, bf16* __restrict__ oh, bf16* __restrict__ ol)
{
    int t = blockIdx.x;
    const float* row = x + (size_t)t * DD;
    float s = 0.f, s2 = 0.f;
    for (int i = threadIdx.x; i < DD; i += 256) {
        float v = row[i]; s += v; s2 += v * v;
    }
    __shared__ float sh[16];
    int warp = threadIdx.x >> 5, lane = threadIdx.x & 31;
    #pragma unroll
    for (int o = 16; o; o >>= 1) {
        s  += __shfl_xor_sync(0xffffffffu, s,  o);
        s2 += __shfl_xor_sync(0xffffffffu, s2, o);
    }
    if (lane == 0) { sh[warp] = s; sh[8 + warp] = s2; }
    __syncthreads();
    if (threadIdx.x == 0) {
        float ts = 0.f, ts2 = 0.f;
        #pragma unroll
        for (int i = 0; i < 8; i++) { ts += sh[i]; ts2 += sh[8 + i]; }
        float mu  = ts  * (1.f / DD);
        float var = ts2 * (1.f / DD) - mu * mu;
        sh[0] = mu; sh[1] = rsqrtf(var + 1e-6f);
    }
    __syncthreads();
    float mu = sh[0], rstd = sh[1];
    for (int i = threadIdx.x; i < DD; i += 256) {
        float y = (row[i] - mu) * rstd * w[i] + b[i];
        split_store(y, oh, ol, (size_t)t * DD + i);
    }
}

// ================= weight transpose + split ================================
__global__ __launch_bounds__(256) void prep_w_kernel(
    const float* __restrict__ W, bf16* __restrict__ Th, bf16* __restrict__ Tl,
    int K, int N)
{
    __shared__ float tile[32][33];
    int n0 = blockIdx.x * 32, k0 = blockIdx.y * 32;
    int tx = threadIdx.x & 31, ty = threadIdx.x >> 5;
    for (int r = ty; r < 32; r += 8)
        tile[r][tx] = W[(size_t)(k0 + r) * N + n0 + tx];
    __syncthreads();
    for (int r = ty; r < 32; r += 8) {
        float v = tile[tx][r];
        split_store(v, Th, Tl, (size_t)(n0 + r) * K + k0 + tx);
    }
}

// ================= mma.sync split-bf16 GEMM ================================
struct GemmJob {
    const bf16 *Ah, *Al, *Bh, *Bl;
    const float *bias, *res;
    float *out;
    bf16 *oh, *ol;
};
struct GemmParams { GemmJob jobs[5]; int K; };

#define PADK 40
#define OPT  (128*PADK)
#define STG  (4*OPT)
#define GSMEM_BYTES (2*STG*2)

__global__ __launch_bounds__(256, 1) void gemm_mma_kernel(GemmParams p)
{
    extern __shared__ bf16 smg[];
    const uint32_t sbase = smem_u32(smg);
    const GemmJob J = p.jobs[blockIdx.z];
    const int K = p.K;
    const int N = gridDim.x * 128;
    const int bm = blockIdx.y * 128, bn = blockIdx.x * 128;
    const int tid = threadIdx.x, lane = tid & 31, wid = tid >> 5;
    const int warpM = wid & 3, warpN = wid >> 2;

    const bf16* gsrc[4];
    gsrc[0] = J.Ah + (size_t)bm * K;
    gsrc[1] = J.Al + (size_t)bm * K;
    gsrc[2] = J.Bh + (size_t)bn * K;
    gsrc[3] = J.Bl + (size_t)bn * K;

    const int lrow = tid >> 1;
    const int lcol = (tid & 1) * 16;
    const uint32_t swr = sbase + (uint32_t)(lrow * PADK + lcol) * 2;

    float acc[2][8][4];
    #pragma unroll
    for (int i = 0; i < 2; i++)
        #pragma unroll
        for (int j = 0; j < 8; j++)
            #pragma unroll
            for (int e = 0; e < 4; e++) acc[i][j][e] = 0.f;

    const int NT = K / 32;
    {
        #pragma unroll
        for (int w = 0; w < 4; w++) {
            const bf16* g = gsrc[w] + (size_t)lrow * K + lcol;
            uint32_t s = swr + (uint32_t)(w * OPT) * 2;
            cp16(s, g); cp16(s + 16, g + 8);
        }
        asm volatile("cp.async.commit_group;");
    }

    int buf = 0;
    for (int kt = 0; kt < NT; kt++) {
        if (kt + 1 < NT) {
            const int k0 = (kt + 1) * 32;
            #pragma unroll
            for (int w = 0; w < 4; w++) {
                const bf16* g = gsrc[w] + (size_t)lrow * K + k0 + lcol;
                uint32_t s = swr + (uint32_t)((buf ^ 1) * STG + w * OPT) * 2;
                cp16(s, g); cp16(s + 16, g + 8);
            }
            asm volatile("cp.async.commit_group;");
            asm volatile("cp.async.wait_group 1;");
        } else {
            asm volatile("cp.async.wait_group 0;");
        }
        __syncthreads();

        const uint32_t stg = sbase + (uint32_t)(buf * STG) * 2;
        #pragma unroll
        for (int ks = 0; ks < 2; ks++) {
            const int koff = ks * 16 + ((lane >> 4) << 3);
            const int rsel = lane & 15;
            uint32_t a[2][2][4], b[2][4][4];
            #pragma unroll
            for (int op = 0; op < 2; op++)
                #pragma unroll
                for (int i = 0; i < 2; i++) {
                    const int row = warpM * 32 + i * 16 + rsel;
                    ldm4(stg + (uint32_t)(op * OPT + row * PADK + koff) * 2,
                         a[op][i]);
                }
            #pragma unroll
            for (int op = 0; op < 2; op++)
                #pragma unroll
                for (int j = 0; j < 4; j++) {
                    const int row = warpN * 64 + j * 16 + rsel;
                    ldm4(stg + (uint32_t)((2 + op) * OPT + row * PADK + koff) * 2,
                         b[op][j]);
                }
            #pragma unroll
            for (int ps = 0; ps < 3; ps++) {
                const int aop = (ps == 2) ? 1 : 0;
                const int bop = (ps == 1) ? 1 : 0;
                #pragma unroll
                for (int i = 0; i < 2; i++)
                    #pragma unroll
                    for (int j = 0; j < 8; j++)
                        mma16816(acc[i][j], a[aop][i],
                                 b[bop][j >> 1][j & 1],
                                 b[bop][j >> 1][(j & 1) + 2]);
            }
        }
        __syncthreads();
        buf ^= 1;
    }

    const int er = (lane >> 2);
    const int ec = (lane & 3) * 2;
    #pragma unroll
    for (int i = 0; i < 2; i++) {
        #pragma unroll
        for (int j = 0; j < 8; j++) {
            const int row0 = bm + warpM * 32 + i * 16 + er;
            const int col0 = bn + warpN * 64 + j * 8 + ec;
            #pragma unroll
            for (int e = 0; e < 4; e++) {
                const int row = row0 + (e >> 1) * 8;
                const int col = col0 + (e & 1);
                float v = acc[i][j][e] + J.bias[col];
                if (J.res) v += J.res[(size_t)row * N + col];
                const size_t idx = (size_t)row * N + col;
                J.out[idx] = v;
                if (J.oh) split_store(v, J.oh, J.ol, idx);
            }
        }
    }
}

// ================= causal feature-conv + silu + split ======================
__global__ __launch_bounds__(256) void conv_silu_kernel(
    const float* __restrict__ xt, const float* __restrict__ cw,
    const float* __restrict__ cbp, float* __restrict__ xc,
    bf16* __restrict__ xch, bf16* __restrict__ xcl)
{
    int t = blockIdx.x;
    int pcol = blockIdx.y * 256 + threadIdx.x;
    const float* row = xt + (size_t)t * PP;
    float w0 = cw[0], w1 = cw[1], w2 = cw[2], w3 = cw[3];
    float acc = row[pcol] * w3;
    if (pcol >= 1) acc += row[pcol - 1] * w2;
    if (pcol >= 2) acc += row[pcol - 2] * w1;
    if (pcol >= 3) acc += row[pcol - 3] * w0;
    acc += cbp[0];
    float y = acc / (1.f + expf(-acc));
    size_t idx = (size_t)t * PP + pcol;
    xc[idx] = y;
    split_store(y, xch, xcl, idx);
}

// ================= i/f gates ===============================================
__global__ __launch_bounds__(256) void gates_kernel(
    const float* __restrict__ xc,
    const float* __restrict__ Wi, const float* __restrict__ bi,
    const float* __restrict__ Wf, const float* __restrict__ bf_,
    float* __restrict__ gi, float* __restrict__ gf)
{
    int t = blockIdx.x;
    int warp = threadIdx.x >> 5, lane = threadIdx.x & 31;
    const float* row = xc + (size_t)t * PP;
    float si = 0.f, sf = 0.f;
    for (int p = lane; p < PP; p += 32) {
        float xv = row[p];
        si += xv * Wi[p * HH + warp];
        sf += xv * Wf[p * HH + warp];
    }
    #pragma unroll
    for (int o = 16; o; o >>= 1) {
        si += __shfl_xor_sync(0xffffffffu, si, o);
        sf += __shfl_xor_sync(0xffffffffu, sf, o);
    }
    if (lane == 0) {
        float a  = si + bi[warp];
        float b2 = sf + bf_[warp];
        gi[t * HH + warp] = 15.f * tanhf(a  * (1.f / 15.f));
        gf[t * HH + warp] = 15.f * tanhf(b2 * (1.f / 15.f));
    }
}

// ================= gate prefix scans (exact linearization) =================
// m_t = F_t + M_t,  F_t = prefix-sum(f),  a_t = i_t - F_t,
// M_t = max(0, prefix-max(a)).  Weight of key j at query t: e^{a_j - M_t}.
__global__ __launch_bounds__(TT) void gatescan_kernel(
    const float* __restrict__ gi, const float* __restrict__ gf,
    float* __restrict__ a_out, float* __restrict__ M_out)
{
    const int bh = blockIdx.x;          // b*HH + h
    const int b = bh >> 3, h = bh & 7;
    const int t = threadIdx.x;
    __shared__ float sf[TT], sa[TT];
    const int gidx = (b * TT + t) * HH + h;
    sf[t] = gf[gidx];
    const float iv = gi[gidx];
    __syncthreads();
    // inclusive prefix sum of f
    #pragma unroll
    for (int st = 1; st < TT; st <<= 1) {
        float add = (t >= st) ? sf[t - st] : 0.f;
        __syncthreads();
        sf[t] += add;
        __syncthreads();
    }
    const float a = iv - sf[t];
    a_out[bh * TT + t] = a;
    sa[t] = a;
    __syncthreads();
    // inclusive prefix max of a
    #pragma unroll
    for (int st = 1; st < TT; st <<= 1) {
        float mx = (t >= st) ? sa[t - st] : -3.4e38f;
        __syncthreads();
        sa[t] = fmaxf(sa[t], mx);
        __syncthreads();
    }
    M_out[bh * TT + t] = fmaxf(0.f, sa[t]);
}

// ================= parallel attention-form scan ============================
// One CTA = 64 queries of one (b,h). Fused epilogue: o-gate sigmoid, head-LN,
// +skip, *silu(r), bf16-split store to comb.
#define QT 64
#define AP 68                       // row pad (floats); 68*4=272B, 16B aligned
#define ASM_BYTES ((4*QT*AP + QT) * 4)

__global__ __launch_bounds__(256) void attn_kernel(
    const float* __restrict__ q, const float* __restrict__ kraw,
    const float* __restrict__ v, const float* __restrict__ aex,
    const float* __restrict__ Mex, const float* __restrict__ oraw,
    const float* __restrict__ skip, const float* __restrict__ rraw,
    const float* __restrict__ hlnw, const float* __restrict__ hlnb,
    bf16* __restrict__ outh, bf16* __restrict__ outl)
{
    const int bh = blockIdx.y, b = bh >> 3, h = bh & 7;
    const int t0 = blockIdx.x * QT;
    extern __shared__ float sm[];
    float* ks = sm;                  // [64][AP]
    float* vs = ks + QT * AP;
    float* qs = vs + QT * AP;
    float* ss = qs + QT * AP;
    float* as_ = ss + QT * AP;       // [64]

    const int tid = threadIdx.x;
    const int qi = tid >> 2, sub = tid & 3;
    const int tq = t0 + qi;
    const size_t qbase = (size_t)(b * TT + tq) * HD + h * DH;

    // load q tile (coalesced: 4 threads per row, 16 floats each)
    {
        const int lr = tid >> 2, lc = (tid & 3) * 16;
        const float* src = q + (size_t)(b * TT + t0 + lr) * HD + h * DH + lc;
        #pragma unroll
        for (int i = 0; i < 16; i += 4)
            *(float4*)&qs[lr * AP + lc + i] = *(const float4*)(src + i);
    }
    __syncthreads();

    const float Mt = Mex[bh * TT + tq];
    float num[16];
    #pragma unroll
    for (int i = 0; i < 16; i++) num[i] = 0.f;
    float den = 0.f;

    for (int j0 = 0; j0 <= t0; j0 += QT) {
        // load k, v tiles + a
        {
            const int lr = tid >> 2, lc = (tid & 3) * 16;
            const size_t gb = (size_t)(b * TT + j0 + lr) * HD + h * DH + lc;
            #pragma unroll
            for (int i = 0; i < 16; i += 4) {
                *(float4*)&ks[lr * AP + lc + i] = *(const float4*)(kraw + gb + i);
                *(float4*)&vs[lr * AP + lc + i] = *(const float4*)(v + gb + i);
            }
            if (tid < QT) as_[tid] = aex[bh * TT + j0 + tid];
        }
        __syncthreads();

        // phase 1: scores s[qi][j] for j = sub + 4*jj
        float sc[16];
        #pragma unroll
        for (int jj = 0; jj < 16; jj++) sc[jj] = 0.f;
        const float* qrow = &qs[qi * AP];
        #pragma unroll 4
        for (int d = 0; d < DH; d += 4) {
            float q0 = qrow[d], q1 = qrow[d+1], q2 = qrow[d+2], q3 = qrow[d+3];
            #pragma unroll
            for (int jj = 0; jj < 16; jj++) {
                const float* kr = &ks[(sub + 4*jj) * AP + d];
                sc[jj] += q0*kr[0] + q1*kr[1] + q2*kr[2] + q3*kr[3];
            }
        }
        const bool diag = (j0 == t0);
        #pragma unroll
        for (int jj = 0; jj < 16; jj++) {
            const int j = sub + 4*jj;
            float w = (diag && j > qi) ? 0.f
                      : __expf(as_[j] - Mt) * 0.125f * sc[jj];
            ss[qi * AP + j] = w;
            den += w;
        }
        __syncthreads();

        // phase 2: num[dd] over dims d = sub + 4*dd
        #pragma unroll 8
        for (int j = 0; j < QT; j++) {
            const float s = ss[qi * AP + j];
            const float* vr = &vs[j * AP + sub];
            #pragma unroll
            for (int dd = 0; dd < 16; dd++)
                num[dd] += s * vr[4*dd];
        }
        __syncthreads();
    }

    // reduce den over the 4 subs of this query, add n0 term
    float sumq = 0.f;
    #pragma unroll
    for (int dd = 0; dd < 16; dd++) sumq += qs[qi * AP + sub + 4*dd];
    den  += __shfl_xor_sync(0xffffffffu, den, 1);
    den  += __shfl_xor_sync(0xffffffffu, den, 2);
    sumq += __shfl_xor_sync(0xffffffffu, sumq, 1);
    sumq += __shfl_xor_sync(0xffffffffu, sumq, 2);
    den = fmaxf(den + __expf(-Mt) * sumq, 1.0f);
    const float rden = 1.f / den;

    // epilogue: o-gate, head layernorm, +skip, *silu(r)
    float hh[16], s1 = 0.f, s2 = 0.f;
    #pragma unroll
    for (int dd = 0; dd < 16; dd++) {
        const int d = sub + 4*dd;
        const float ov = oraw[qbase + d];
        const float og = 1.f / (1.f + __expf(-ov));
        const float hv = og * num[dd] * rden;
        hh[dd] = hv;
        s1 += hv; s2 += hv * hv;
    }
    s1 += __shfl_xor_sync(0xffffffffu, s1, 1);
    s1 += __shfl_xor_sync(0xffffffffu, s1, 2);
    s2 += __shfl_xor_sync(0xffffffffu, s2, 1);
    s2 += __shfl_xor_sync(0xffffffffu, s2, 2);
    const float mu  = s1 * (1.f / DH);
    const float var = s2 * (1.f / DH) - mu * mu;
    const float rstd = rsqrtf(var + 1e-6f);
    #pragma unroll
    for (int dd = 0; dd < 16; dd++) {
        const int d = sub + 4*dd;
        const float hn = (hh[dd] - mu) * rstd * hlnw[h*DH + d] + hlnb[h*DH + d];
        const float rv = rraw[qbase + d];
        const float sil = rv / (1.f + __expf(-rv));
        const float val = (hn + skip[qbase + d]) * sil;
        split_store(val, outh, outl, qbase + d);
    }
}

// ===========================================================================
extern "C" void kernel_launch(void* const* d_in, const int* in_sizes, int n_in,
                              void* d_out, int out_size)
{
    const float* x      = (const float*)d_in[0];
    const float* ln_w   = (const float*)d_in[1];
    const float* ln_b   = (const float*)d_in[2];
    const float* hln_w  = (const float*)d_in[3];
    const float* hln_b  = (const float*)d_in[4];
    const float* Wl     = (const float*)d_in[5];
    const float* bl     = (const float*)d_in[6];
    const float* Wr     = (const float*)d_in[7];
    const float* br     = (const float*)d_in[8];
    const float* conv_w = (const float*)d_in[9];
    const float* conv_b = (const float*)d_in[10];
    const float* Wskip  = (const float*)d_in[11];
    const float* bskip  = (const float*)d_in[12];
    const float* Wi     = (const float*)d_in[13];
    const float* bi     = (const float*)d_in[14];
    const float* Wf     = (const float*)d_in[15];
    const float* bf_    = (const float*)d_in[16];
    const float* Wo     = (const float*)d_in[17];
    const float* bo     = (const float*)d_in[18];
    const float* Wq     = (const float*)d_in[19];
    const float* bq     = (const float*)d_in[20];
    const float* Wk     = (const float*)d_in[21];
    const float* bk     = (const float*)d_in[22];
    const float* Wv     = (const float*)d_in[23];
    const float* bv     = (const float*)d_in[24];
    const float* Wd     = (const float*)d_in[25];
    const float* bd     = (const float*)d_in[26];
    float* out = (float*)d_out;

    bf16 *xn_h, *xn_l, *xt_h, *xt_l, *xc_h, *xc_l, *cm_h, *cm_l;
    bf16 *WlT_h, *WlT_l, *WrT_h, *WrT_l, *WsT_h, *WsT_l, *WqT_h, *WqT_l;
    bf16 *WkT_h, *WkT_l, *WvT_h, *WvT_l, *WoT_h, *WoT_l, *WdT_h, *WdT_l;
    float *xt, *xc, *r, *skip, *q, *k, *v, *o, *gi, *gf, *aex, *Mex;
    cudaGetSymbolAddress((void**)&xn_h, g_xn_h);  cudaGetSymbolAddress((void**)&xn_l, g_xn_l);
    cudaGetSymbolAddress((void**)&xt,   g_xt);
    cudaGetSymbolAddress((void**)&xt_h, g_xt_h);  cudaGetSymbolAddress((void**)&xt_l, g_xt_l);
    cudaGetSymbolAddress((void**)&xc,   g_xc);
    cudaGetSymbolAddress((void**)&xc_h, g_xc_h);  cudaGetSymbolAddress((void**)&xc_l, g_xc_l);
    cudaGetSymbolAddress((void**)&r,    g_r);     cudaGetSymbolAddress((void**)&skip, g_skip);
    cudaGetSymbolAddress((void**)&q,    g_q);     cudaGetSymbolAddress((void**)&k,    g_k);
    cudaGetSymbolAddress((void**)&v,    g_v);     cudaGetSymbolAddress((void**)&o,    g_o);
    cudaGetSymbolAddress((void**)&gi,   g_ig);    cudaGetSymbolAddress((void**)&gf,   g_fg);
    cudaGetSymbolAddress((void**)&aex,  g_a);     cudaGetSymbolAddress((void**)&Mex,  g_M);
    cudaGetSymbolAddress((void**)&cm_h, g_cm_h);  cudaGetSymbolAddress((void**)&cm_l, g_cm_l);
    cudaGetSymbolAddress((void**)&WlT_h, g_WlT_h); cudaGetSymbolAddress((void**)&WlT_l, g_WlT_l);
    cudaGetSymbolAddress((void**)&WrT_h, g_WrT_h); cudaGetSymbolAddress((void**)&WrT_l, g_WrT_l);
    cudaGetSymbolAddress((void**)&WsT_h, g_WsT_h); cudaGetSymbolAddress((void**)&WsT_l, g_WsT_l);
    cudaGetSymbolAddress((void**)&WqT_h, g_WqT_h); cudaGetSymbolAddress((void**)&WqT_l, g_WqT_l);
    cudaGetSymbolAddress((void**)&WkT_h, g_WkT_h); cudaGetSymbolAddress((void**)&WkT_l, g_WkT_l);
    cudaGetSymbolAddress((void**)&WvT_h, g_WvT_h); cudaGetSymbolAddress((void**)&WvT_l, g_WvT_l);
    cudaGetSymbolAddress((void**)&WoT_h, g_WoT_h); cudaGetSymbolAddress((void**)&WoT_l, g_WoT_l);
    cudaGetSymbolAddress((void**)&WdT_h, g_WdT_h); cudaGetSymbolAddress((void**)&WdT_l, g_WdT_l);

    cudaFuncSetAttribute(gemm_mma_kernel,
                         cudaFuncAttributeMaxDynamicSharedMemorySize, GSMEM_BYTES);
    cudaFuncSetAttribute(attn_kernel,
                         cudaFuncAttributeMaxDynamicSharedMemorySize, ASM_BYTES);

    // weight prep: transpose + bf16 split
    prep_w_kernel<<<dim3(PP/32, DD/32), 256>>>(Wl,    WlT_h, WlT_l, DD, PP);
    prep_w_kernel<<<dim3(HD/32, DD/32), 256>>>(Wr,    WrT_h, WrT_l, DD, HD);
    prep_w_kernel<<<dim3(HD/32, PP/32), 256>>>(Wskip, WsT_h, WsT_l, PP, HD);
    prep_w_kernel<<<dim3(HD/32, PP/32), 256>>>(Wq,    WqT_h, WqT_l, PP, HD);
    prep_w_kernel<<<dim3(HD/32, PP/32), 256>>>(Wk,    WkT_h, WkT_l, PP, HD);
    prep_w_kernel<<<dim3(HD/32, PP/32), 256>>>(Wv,    WvT_h, WvT_l, PP, HD);
    prep_w_kernel<<<dim3(HD/32, PP/32), 256>>>(Wo,    WoT_h, WoT_l, PP, HD);
    prep_w_kernel<<<dim3(DD/32, HD/32), 256>>>(Wd,    WdT_h, WdT_l, HD, DD);

    // 1. layernorm -> xn splits
    ln_split_kernel<<<NTOK, 256>>>(x, ln_w, ln_b, xn_h, xn_l);

    // 2. xt = xn @ Wl + bl
    {
        GemmParams p{}; p.K = DD;
        p.jobs[0] = { xn_h, xn_l, WlT_h, WlT_l, bl, nullptr, xt, xt_h, xt_l };
        gemm_mma_kernel<<<dim3(PP/128, NTOK/128, 1), 256, GSMEM_BYTES>>>(p);
    }
    // 3. r = xn @ Wr + br
    {
        GemmParams p{}; p.K = DD;
        p.jobs[0] = { xn_h, xn_l, WrT_h, WrT_l, br, nullptr, r, nullptr, nullptr };
        gemm_mma_kernel<<<dim3(HD/128, NTOK/128, 1), 256, GSMEM_BYTES>>>(p);
    }
    // 4. conv + silu -> xc
    conv_silu_kernel<<<dim3(NTOK, PP/256), 256>>>(xt, conv_w, conv_b, xc, xc_h, xc_l);

    // 5. five P->HD projections in one batched launch
    {
        GemmParams p{}; p.K = PP;
        p.jobs[0] = { xc_h, xc_l, WsT_h, WsT_l, bskip, nullptr, skip, nullptr, nullptr };
        p.jobs[1] = { xc_h, xc_l, WqT_h, WqT_l, bq,    nullptr, q,    nullptr, nullptr };
        p.jobs[2] = { xc_h, xc_l, WkT_h, WkT_l, bk,    nullptr, k,    nullptr, nullptr };
        p.jobs[3] = { xt_h, xt_l, WvT_h, WvT_l, bv,    nullptr, v,    nullptr, nullptr };
        p.jobs[4] = { xt_h, xt_l, WoT_h, WoT_l, bo,    nullptr, o,    nullptr, nullptr };
        gemm_mma_kernel<<<dim3(HD/128, NTOK/128, 5), 256, GSMEM_BYTES>>>(p);
    }
    // 6. i/f gates + prefix scans
    gates_kernel<<<NTOK, 256>>>(xc, Wi, bi, Wf, bf_, gi, gf);
    gatescan_kernel<<<BB*HH, TT>>>(gi, gf, aex, Mex);

    // 7. parallel attention-form scan -> comb splits
    attn_kernel<<<dim3(TT/QT, BB*HH), 256, ASM_BYTES>>>(
        q, k, v, aex, Mex, o, skip, r, hln_w, hln_b, cm_h, cm_l);

    // 8. out = comb @ Wd + bd + x
    {
        GemmParams p{}; p.K = HD;
        p.jobs[0] = { cm_h, cm_l, WdT_h, WdT_l, bd, x, out, nullptr, nullptr };
        gemm_mma_kernel<<<dim3(DD/128, NTOK/128, 1), 256, GSMEM_BYTES>>>(p);
    }
}